// round 4
// baseline (speedup 1.0000x reference)
#include <cuda_runtime.h>
#include <cuda_bf16.h>

#define NX 192
#define NY 192
#define NZ 192
#define PLANE (NY * NZ)          // 36864
#define VOL   (NX * PLANE)       // 7077888 per channel per batch
#define NBLOCKS (48 * 192 * 2)   // 18432 partial sums
#define NVOX  (2.0 * NX * NY * NZ) // 14155776 voxels per mean

// Scratch for deterministic two-stage reduction (no device allocation allowed).
__device__ float g_partials[NBLOCKS];

__device__ __forceinline__ float4 ld4(const float* __restrict__ p) {
    return *reinterpret_cast<const float4*>(p);
}

// Huber-like robust penalty from the reference, delta = 0.01
__device__ __forceinline__ float robustf(float x) {
    float ax = fabsf(x);
    return (ax <= 0.01f) ? 0.5f * x * x : 0.01f * (ax - 0.005f);
}

// Compute jnp.gradient along x (axis1), y (axis2), z (axis3) for 4 consecutive
// z-voxels of one channel. Central differences interior, one-sided at edges.
__device__ __forceinline__ void grads(const float* __restrict__ p,
                                      int x, int y, int z0,
                                      float gx[4], float gy[4], float gz[4]) {
    const size_t base = (size_t)x * PLANE + (size_t)y * NZ + (size_t)z0;
    float4 c = ld4(p + base);

    // x direction (stride = PLANE)
    float4 xm = (x > 0)      ? ld4(p + base - PLANE) : c;
    float4 xp = (x < NX - 1) ? ld4(p + base + PLANE) : c;
    float sx  = (x > 0 && x < NX - 1) ? 0.5f : 1.0f;
    gx[0] = (xp.x - xm.x) * sx;
    gx[1] = (xp.y - xm.y) * sx;
    gx[2] = (xp.z - xm.z) * sx;
    gx[3] = (xp.w - xm.w) * sx;

    // y direction (stride = NZ)
    float4 ym = (y > 0)      ? ld4(p + base - NZ) : c;
    float4 yp = (y < NY - 1) ? ld4(p + base + NZ) : c;
    float sy  = (y > 0 && y < NY - 1) ? 0.5f : 1.0f;
    gy[0] = (yp.x - ym.x) * sy;
    gy[1] = (yp.y - ym.y) * sy;
    gy[2] = (yp.z - ym.z) * sy;
    gy[3] = (yp.w - ym.w) * sy;

    // z direction (contiguous): neighbors mostly inside the float4
    float zm = (z0 > 0)      ? p[base - 1] : 0.0f;
    float zp = (z0 < NZ - 4) ? p[base + 4] : 0.0f;
    gz[0] = (z0 > 0)      ? (c.y - zm) * 0.5f : (c.y - c.x);
    gz[1] = (c.z - c.x) * 0.5f;
    gz[2] = (c.w - c.y) * 0.5f;
    gz[3] = (z0 < NZ - 4) ? (zp - c.z) * 0.5f : (c.w - c.z);
}

__global__ __launch_bounds__(192)
void elastic_kernel(const float* __restrict__ df) {
    const int zg = threadIdx.x;                     // 0..47 -> z0 = 4*zg
    const int y  = blockIdx.x * 4 + threadIdx.y;    // 0..191
    const int x  = blockIdx.y;                      // 0..191
    const int b  = blockIdx.z;                      // 0..1
    const int z0 = zg * 4;

    const float* u = df + (size_t)(b * 3 + 0) * VOL;
    const float* v = df + (size_t)(b * 3 + 1) * VOL;
    const float* w = df + (size_t)(b * 3 + 2) * VOL;

    float ugx[4], ugy[4], ugz[4];
    float vgx[4], vgy[4], vgz[4];
    float wgx[4], wgy[4], wgz[4];
    grads(u, x, y, z0, ugx, ugy, ugz);
    grads(v, x, y, z0, vgx, vgy, vgz);
    grads(w, x, y, z0, wgx, wgy, wgz);

    float acc = 0.0f;
    #pragma unroll
    for (int i = 0; i < 4; i++) {
        float ux = ugx[i], uy = ugy[i], uz = ugz[i];
        float vx = vgx[i], vy = vgy[i], vz = vgz[i];
        float wx = wgx[i], wy = wgy[i], wz = wgz[i];

        float exy = 0.5f * (uy + vx);
        float exz = 0.5f * (uz + wx);
        float eyz = 0.5f * (vz + wy);
        float tr  = ux + vy + wz;

        float rt  = robustf(tr);
        float rxx = robustf(ux);
        float ryy = robustf(vy);
        float rzz = robustf(wz);
        float rxy = robustf(exy);
        float rxz = robustf(exz);
        float ryz = robustf(eyz);

        // lambda=1.0, mu=0.5
        float energy = 0.5f * rt * rt
                     + 0.5f * (rxx * rxx + ryy * ryy + rzz * rzz
                               + 2.0f * (rxy * rxy + rxz * rxz + ryz * ryz));

        // Jacobian exactly as written in the reference (NOT the true determinant:
        // the 2nd and 3rd cofactors use (1+dw_dx) where a det would use dw_dx).
        float jac = (1.0f + ux) * ((1.0f + vy) * (1.0f + wz) - vz * wy)
                  - uy * (vx * (1.0f + wz) - vz * (1.0f + wx))
                  + uz * (vx * wy - (1.0f + vy) * (1.0f + wx));

        float pen = fmaxf(-jac, 0.0f);   // relu(-jac)
        acc += energy + 0.1f * pen;
    }

    // Block reduction (192 threads, pad shared to 256 for power-of-two tree)
    __shared__ float sdata[256];
    int t = threadIdx.y * 48 + threadIdx.x;
    sdata[t] = acc;
    if (t < 64) sdata[192 + t] = 0.0f;
    __syncthreads();
    #pragma unroll
    for (int s = 128; s > 0; s >>= 1) {
        if (t < s) sdata[t] += sdata[t + s];
        __syncthreads();
    }
    if (t == 0) {
        int bid = (blockIdx.z * 192 + blockIdx.y) * 48 + blockIdx.x;
        g_partials[bid] = sdata[0];
    }
}

__global__ __launch_bounds__(256)
void reduce_kernel(float* __restrict__ out) {
    __shared__ double sd[256];
    double s = 0.0;
    for (int i = threadIdx.x; i < NBLOCKS; i += 256)
        s += (double)g_partials[i];
    sd[threadIdx.x] = s;
    __syncthreads();
    #pragma unroll
    for (int st = 128; st > 0; st >>= 1) {
        if (threadIdx.x < st) sd[threadIdx.x] += sd[threadIdx.x + st];
        __syncthreads();
    }
    if (threadIdx.x == 0)
        out[0] = (float)(sd[0] / NVOX);
}

extern "C" void kernel_launch(void* const* d_in, const int* in_sizes, int n_in,
                              void* d_out, int out_size) {
    const float* df = (const float*)d_in[0];
    dim3 block(48, 4, 1);
    dim3 grid(48, 192, 2);
    elastic_kernel<<<grid, block>>>(df);
    reduce_kernel<<<1, 256>>>((float*)d_out);
}